// round 14
// baseline (speedup 1.0000x reference)
#include <cuda_runtime.h>
#include <cuda_bf16.h>
#include <cstdint>

// Problem shape
#define B_ROWS 8192
#define K_DIM  512
#define C_COLS 4096

constexpr int TM  = 128;              // M tile
constexpr int TN  = 128;              // N tile
constexpr int KC  = 64;               // K chunk (64 bf16 = 128B row)
constexpr int NKC = K_DIM / KC;       // 8
constexpr int MT  = B_ROWS / TM;      // 64
constexpr int NT  = C_COLS / TN;      // 32
constexpr int CHUNK_BYTES = 128 * 128; // one (tile, kchunk) block: 128 rows x 128B = 16KB

// ---- scratch (static device memory; no allocation) ----
__device__ __align__(1024) unsigned char g_A [(size_t)B_ROWS * K_DIM * 2]; // bf16 x, tiled+swizzled
__device__ __align__(1024) unsigned char g_Bt[(size_t)C_COLS * K_DIM * 2]; // bf16 w^T, tiled+swizzled
__device__ float g_xn[B_ROWS];   // ||x_b||^2
__device__ float g_p [C_COLS];   // 1/s^2
__device__ float g_q [C_COLS];   // ||w_c||^2 / (2 s^2)

// ============================ PTX helpers (family-safe: no tcgen05/TMEM) ====
__device__ __forceinline__ uint32_t smem_u32(const void* p) {
    uint32_t a;
    asm("{ .reg .u64 t; cvta.to.shared.u64 t, %1; cvt.u32.u64 %0, t; }" : "=r"(a) : "l"(p));
    return a;
}

__device__ __forceinline__ void cp_async16(uint32_t dst, const void* src) {
    asm volatile("cp.async.cg.shared.global [%0], [%1], 16;" :: "r"(dst), "l"(src) : "memory");
}
#define CP_ASYNC_COMMIT() asm volatile("cp.async.commit_group;" ::: "memory")
template <int N>
__device__ __forceinline__ void cp_async_wait_group() {
    asm volatile("cp.async.wait_group %0;" :: "n"(N) : "memory");
}

__device__ __forceinline__ void ldmatrix_x4(uint32_t* r, uint32_t addr) {
    asm volatile("ldmatrix.sync.aligned.m8n8.x4.shared.b16 {%0,%1,%2,%3}, [%4];"
                 : "=r"(r[0]), "=r"(r[1]), "=r"(r[2]), "=r"(r[3]) : "r"(addr));
}

// D += A*B, m16n8k16, row.col, bf16 in / fp32 accum
__device__ __forceinline__ void mma16816(float* d, const uint32_t* a, uint32_t b0, uint32_t b1) {
    asm volatile(
        "mma.sync.aligned.m16n8k16.row.col.f32.bf16.bf16.f32 "
        "{%0,%1,%2,%3}, {%4,%5,%6,%7}, {%8,%9}, {%0,%1,%2,%3};"
        : "+f"(d[0]), "+f"(d[1]), "+f"(d[2]), "+f"(d[3])
        : "r"(a[0]), "r"(a[1]), "r"(a[2]), "r"(a[3]), "r"(b0), "r"(b1));
}

// streaming (evict-first) 8B store: keeps A/B operands resident in L2
__device__ __forceinline__ void stcs_f2(float* p, float2 v) {
    asm volatile("st.global.cs.v2.f32 [%0], {%1, %2};" :: "l"(p), "f"(v.x), "f"(v.y) : "memory");
}

// ============================ prepass kernels ============================
// x [B,K] fp32 -> g_A bf16, layout: [mt][kc] 16KB blocks of 128 rows x 128B,
// XOR-swizzled at 16B granularity: stored_chunk = chunk ^ (row&7).
__global__ void pack_x_kernel(const float* __restrict__ x) {
    unsigned id = blockIdx.x * blockDim.x + threadIdx.x;  // 524288 16B-chunks
    unsigned c4 = id & 7u, r = (id >> 3) & 127u, kc = (id >> 10) & 7u, mt = id >> 13;
    unsigned m = mt * 128u + r;
    const float4* src = reinterpret_cast<const float4*>(x + (size_t)m * K_DIM + kc * 64u + c4 * 8u);
    float4 a = src[0], b = src[1];
    __nv_bfloat162 h0 = __floats2bfloat162_rn(a.x, a.y);
    __nv_bfloat162 h1 = __floats2bfloat162_rn(a.z, a.w);
    __nv_bfloat162 h2 = __floats2bfloat162_rn(b.x, b.y);
    __nv_bfloat162 h3 = __floats2bfloat162_rn(b.z, b.w);
    uint4 v;
    v.x = *reinterpret_cast<uint32_t*>(&h0);
    v.y = *reinterpret_cast<uint32_t*>(&h1);
    v.z = *reinterpret_cast<uint32_t*>(&h2);
    v.w = *reinterpret_cast<uint32_t*>(&h3);
    size_t dst = ((size_t)((mt * NKC + kc) * 128u + r) * 8u + (c4 ^ (r & 7u))) * 16u;
    *reinterpret_cast<uint4*>(g_A + dst) = v;
}

// w [K,C] fp32 -> g_Bt bf16 transposed: Bt[n,k] = w[k,n], same tiled+swizzled layout.
__global__ void pack_w_kernel(const float* __restrict__ w) {
    unsigned id = blockIdx.x * blockDim.x + threadIdx.x;  // 262144 16B-chunks
    unsigned c4 = id & 7u, r = (id >> 3) & 127u, kc = (id >> 10) & 7u, nt = id >> 13;
    unsigned n = nt * 128u + r;
    unsigned kb = kc * 64u + c4 * 8u;
    float f[8];
#pragma unroll
    for (int j = 0; j < 8; j++) f[j] = w[(size_t)(kb + j) * C_COLS + n];
    __nv_bfloat162 h0 = __floats2bfloat162_rn(f[0], f[1]);
    __nv_bfloat162 h1 = __floats2bfloat162_rn(f[2], f[3]);
    __nv_bfloat162 h2 = __floats2bfloat162_rn(f[4], f[5]);
    __nv_bfloat162 h3 = __floats2bfloat162_rn(f[6], f[7]);
    uint4 v;
    v.x = *reinterpret_cast<uint32_t*>(&h0);
    v.y = *reinterpret_cast<uint32_t*>(&h1);
    v.z = *reinterpret_cast<uint32_t*>(&h2);
    v.w = *reinterpret_cast<uint32_t*>(&h3);
    size_t dst = ((size_t)((nt * NKC + kc) * 128u + r) * 8u + (c4 ^ (r & 7u))) * 16u;
    *reinterpret_cast<uint4*>(g_Bt + dst) = v;
}

// ||x_b||^2 (fp32, one warp per row)
__global__ void xnorm_kernel(const float* __restrict__ x) {
    int wid = threadIdx.x >> 5, lid = threadIdx.x & 31;
    int row = blockIdx.x * 8 + wid;
    const float4* src = reinterpret_cast<const float4*>(x + (size_t)row * K_DIM);
    float sum = 0.f;
#pragma unroll
    for (int i = 0; i < 4; i++) {
        float4 v = src[lid + 32 * i];
        sum = fmaf(v.x, v.x, sum); sum = fmaf(v.y, v.y, sum);
        sum = fmaf(v.z, v.z, sum); sum = fmaf(v.w, v.w, sum);
    }
#pragma unroll
    for (int off = 16; off; off >>= 1) sum += __shfl_xor_sync(0xFFFFFFFFu, sum, off);
    if (lid == 0) g_xn[row] = sum;
}

// per-column constants: p = 1/s^2, q = ||w_c||^2 / (2 s^2)
__global__ void wstats_kernel(const float* __restrict__ w, const float* __restrict__ s) {
    int c = blockIdx.x * blockDim.x + threadIdx.x;
    float sum = 0.f;
#pragma unroll 8
    for (int k = 0; k < K_DIM; k++) {
        float v = w[(size_t)k * C_COLS + c];
        sum = fmaf(v, v, sum);
    }
    float sv = s[c];
    float p = 1.0f / (sv * sv);
    g_p[c] = p;
    g_q[c] = 0.5f * sum * p;
}

// ============================ GEMM + epilogue ============================
// smem: A0 A1 B0 B1, 16KB each. 256 threads: each copies 4 x 16B per tile.
__device__ __forceinline__ void load_chunk(uint32_t sb, int mt, int nt, int c, int buf, int tid) {
    const unsigned char* gA = g_A  + (size_t)(mt * NKC + c) * CHUNK_BYTES;
    const unsigned char* gB = g_Bt + (size_t)(nt * NKC + c) * CHUNK_BYTES;
    uint32_t sA = sb + buf * CHUNK_BYTES;
    uint32_t sB = sb + 2 * CHUNK_BYTES + buf * CHUNK_BYTES;
#pragma unroll
    for (int i = 0; i < 4; i++) {
        int o = (tid + i * 256) * 16;
        cp_async16(sA + o, gA + o);
    }
#pragma unroll
    for (int i = 0; i < 4; i++) {
        int o = (tid + i * 256) * 16;
        cp_async16(sB + o, gB + o);
    }
    CP_ASYNC_COMMIT();
}

__global__ __launch_bounds__(256) void rbf_gemm_kernel(float* __restrict__ out) {
    extern __shared__ __align__(1024) unsigned char smem[]; // 64KB
    __shared__ float s_p[TN], s_q[TN], s_xn[TM];

    int tid = threadIdx.x, lane = tid & 31, wid = tid >> 5;
    int wm = wid >> 1;          // 0..3 -> 32-row block
    int wn = wid & 1;           // 0..1 -> 64-col block
    int nt = blockIdx.x, mt = blockIdx.y;
    uint32_t sb = smem_u32(smem);

    if (tid < TN) {
        s_p[tid]  = g_p[nt * TN + tid];
        s_q[tid]  = g_q[nt * TN + tid];
        s_xn[tid] = g_xn[mt * TM + tid];
    }
    load_chunk(sb, mt, nt, 0, 0, tid);   // preload chunk 0

    float d[2][8][4];
#pragma unroll
    for (int mi = 0; mi < 2; mi++)
#pragma unroll
        for (int ni = 0; ni < 8; ni++)
#pragma unroll
            for (int j = 0; j < 4; j++) d[mi][ni][j] = 0.f;

    unsigned row16 = (unsigned)(lane & 15);  // ldmatrix row within 16-row block
    unsigned t     = (unsigned)(lane >> 4);  // 16B chunk parity (k8 half)

#pragma unroll 1
    for (int c = 0; c < NKC; c++) {
        if (c + 1 < NKC) load_chunk(sb, mt, nt, c + 1, (c + 1) & 1, tid);
        if (c + 1 < NKC) cp_async_wait_group<1>(); else cp_async_wait_group<0>();
        __syncthreads();

        uint32_t sA = sb + (c & 1) * CHUNK_BYTES;
        uint32_t sB = sb + 2 * CHUNK_BYTES + (c & 1) * CHUNK_BYTES;
#pragma unroll
        for (unsigned s = 0; s < 4; s++) {      // 4 x k16 steps cover KC=64
            uint32_t a[2][4];
#pragma unroll
            for (unsigned mi = 0; mi < 2; mi++) {
                unsigned row = (unsigned)wm * 32u + mi * 16u + row16;
                unsigned chunk = (t ^ (row & 7u)) ^ (2u * s);
                ldmatrix_x4(a[mi], sA + row * 128u + (chunk << 4));
            }
            uint32_t bb[4][4];
#pragma unroll
            for (unsigned nj = 0; nj < 4; nj++) {
                unsigned nrow = (unsigned)wn * 64u + nj * 16u + row16;
                unsigned chunk = (t ^ (nrow & 7u)) ^ (2u * s);
                ldmatrix_x4(bb[nj], sB + nrow * 128u + (chunk << 4));
            }
#pragma unroll
            for (int mi = 0; mi < 2; mi++)
#pragma unroll
                for (int ni = 0; ni < 8; ni++) {
                    int nj = ni >> 1, h = ni & 1;
                    mma16816(d[mi][ni], a[mi], bb[nj][h], bb[nj][h + 2]);
                }
        }
        __syncthreads();   // all warps done with buf (c&1) before it is refilled
    }

    // epilogue: arg = (xw - 0.5*||x||^2)*p_c - q_c ; out = exp(arg), with exact
    // flush-to-zero fast path (fp32 exp underflows to 0 for arg < -103.98).
    // Streaming stores (.cs): output is write-once; don't evict L2-resident A/B.
#pragma unroll
    for (int mi = 0; mi < 2; mi++) {
        int rloc = wm * 32 + mi * 16 + (lane >> 2);
        float h0 = 0.5f * s_xn[rloc];
        float h1 = 0.5f * s_xn[rloc + 8];
        float* row0 = out + (size_t)(mt * TM + rloc) * C_COLS + nt * TN + wn * 64;
        float* row1 = row0 + 8 * C_COLS;
#pragma unroll
        for (int ni = 0; ni < 8; ni++) {
            int cl = wn * 64 + ni * 8 + (lane & 3) * 2;
            float p0 = s_p[cl], p1 = s_p[cl + 1];
            float q0 = s_q[cl], q1 = s_q[cl + 1];
            float a0 = fmaf(d[mi][ni][0] - h0, p0, -q0);
            float a1 = fmaf(d[mi][ni][1] - h0, p1, -q1);
            float a2 = fmaf(d[mi][ni][2] - h1, p0, -q0);
            float a3 = fmaf(d[mi][ni][3] - h1, p1, -q1);
            float2 v01, v23;
            v01.x = (a0 > -110.0f) ? __expf(a0) : 0.0f;
            v01.y = (a1 > -110.0f) ? __expf(a1) : 0.0f;
            v23.x = (a2 > -110.0f) ? __expf(a2) : 0.0f;
            v23.y = (a3 > -110.0f) ? __expf(a3) : 0.0f;
            int off = ni * 8 + (lane & 3) * 2;
            stcs_f2(row0 + off, v01);
            stcs_f2(row1 + off, v23);
        }
    }
}

// ============================ launch ============================
extern "C" void kernel_launch(void* const* d_in, const int* in_sizes, int n_in,
                              void* d_out, int out_size) {
    const float* x = (const float*)d_in[0];   // [8192, 512]
    const float* w = (const float*)d_in[1];   // [512, 4096]
    const float* s = (const float*)d_in[2];   // [1, 4096]
    float* out = (float*)d_out;               // [8192, 4096]

    (void)cudaFuncSetAttribute(rbf_gemm_kernel,
                               cudaFuncAttributeMaxDynamicSharedMemorySize, 4 * CHUNK_BYTES);

    pack_x_kernel<<<2048, 256>>>(x);
    xnorm_kernel<<<B_ROWS / 8, 256>>>(x);
    pack_w_kernel<<<1024, 256>>>(w);
    wstats_kernel<<<C_COLS / 256, 256>>>(w, s);

    dim3 grid(NT, MT);   // (32, 64)
    rbf_gemm_kernel<<<grid, 256, 4 * CHUNK_BYTES>>>(out);
}

// round 17
// speedup vs baseline: 1.1147x; 1.1147x over previous
#include <cuda_runtime.h>
#include <cuda_bf16.h>
#include <cstdint>

// Problem shape
#define B_ROWS 8192
#define K_DIM  512
#define C_COLS 4096

constexpr int TM  = 128;              // M tile
constexpr int TN  = 128;              // N tile
constexpr int KC  = 64;               // K chunk (64 bf16 = 128B row)
constexpr int NKC = K_DIM / KC;       // 8
constexpr int MT  = B_ROWS / TM;      // 64
constexpr int NT  = C_COLS / TN;      // 32
constexpr int CHUNK_BYTES = 128 * 128; // one (tile, kchunk) block: 128 rows x 128B = 16KB

// ---- scratch (static device memory; no allocation) ----
__device__ __align__(1024) unsigned char g_A [(size_t)B_ROWS * K_DIM * 2]; // bf16 x, tiled+swizzled
__device__ __align__(1024) unsigned char g_Bt[(size_t)C_COLS * K_DIM * 2]; // bf16 w^T, tiled+swizzled
__device__ float g_xpart[(size_t)B_ROWS * 64];  // per-chunk partial ||x||^2 (2 MB)
__device__ float g_wpart[(size_t)C_COLS * 64];  // per-chunk partial ||w_c||^2 (1 MB)
__device__ float g_xn[B_ROWS];   // ||x_b||^2
__device__ float g_p [C_COLS];   // 1/s^2
__device__ float g_q [C_COLS];   // ||w_c||^2 / (2 s^2)

// ============================ PTX helpers (family-safe: no tcgen05/TMEM) ====
__device__ __forceinline__ uint32_t smem_u32(const void* p) {
    uint32_t a;
    asm("{ .reg .u64 t; cvta.to.shared.u64 t, %1; cvt.u32.u64 %0, t; }" : "=r"(a) : "l"(p));
    return a;
}

__device__ __forceinline__ void cp_async16(uint32_t dst, const void* src) {
    asm volatile("cp.async.cg.shared.global [%0], [%1], 16;" :: "r"(dst), "l"(src) : "memory");
}
#define CP_ASYNC_COMMIT() asm volatile("cp.async.commit_group;" ::: "memory")
template <int N>
__device__ __forceinline__ void cp_async_wait_group() {
    asm volatile("cp.async.wait_group %0;" :: "n"(N) : "memory");
}

__device__ __forceinline__ void ldmatrix_x4(uint32_t* r, uint32_t addr) {
    asm volatile("ldmatrix.sync.aligned.m8n8.x4.shared.b16 {%0,%1,%2,%3}, [%4];"
                 : "=r"(r[0]), "=r"(r[1]), "=r"(r[2]), "=r"(r[3]) : "r"(addr));
}

// D += A*B, m16n8k16, row.col, bf16 in / fp32 accum
__device__ __forceinline__ void mma16816(float* d, const uint32_t* a, uint32_t b0, uint32_t b1) {
    asm volatile(
        "mma.sync.aligned.m16n8k16.row.col.f32.bf16.bf16.f32 "
        "{%0,%1,%2,%3}, {%4,%5,%6,%7}, {%8,%9}, {%0,%1,%2,%3};"
        : "+f"(d[0]), "+f"(d[1]), "+f"(d[2]), "+f"(d[3])
        : "r"(a[0]), "r"(a[1]), "r"(a[2]), "r"(a[3]), "r"(b0), "r"(b1));
}

// streaming (evict-first) 8B store: keeps A/B operands resident in L2
__device__ __forceinline__ void stcs_f2(float* p, float2 v) {
    asm volatile("st.global.cs.v2.f32 [%0], {%1, %2};" :: "l"(p), "f"(v.x), "f"(v.y) : "memory");
}

// ============================ prepass kernels ============================
// x [B,K] fp32 -> g_A bf16, layout: [mt][kc] 16KB blocks of 128 rows x 128B,
// XOR-swizzled at 16B granularity: stored_chunk = chunk ^ (row&7).
// Also emits per-8-element partial sum-of-squares (fused ||x||^2 reduction stage 1).
__global__ void pack_x_kernel(const float* __restrict__ x) {
    unsigned id = blockIdx.x * blockDim.x + threadIdx.x;  // 524288 16B-chunks
    unsigned c4 = id & 7u, r = (id >> 3) & 127u, kc = (id >> 10) & 7u, mt = id >> 13;
    unsigned m = mt * 128u + r;
    const float4* src = reinterpret_cast<const float4*>(x + (size_t)m * K_DIM + kc * 64u + c4 * 8u);
    float4 a = src[0], b = src[1];
    float ss = a.x*a.x + a.y*a.y + a.z*a.z + a.w*a.w
             + b.x*b.x + b.y*b.y + b.z*b.z + b.w*b.w;
    g_xpart[(size_t)m * 64u + kc * 8u + c4] = ss;
    __nv_bfloat162 h0 = __floats2bfloat162_rn(a.x, a.y);
    __nv_bfloat162 h1 = __floats2bfloat162_rn(a.z, a.w);
    __nv_bfloat162 h2 = __floats2bfloat162_rn(b.x, b.y);
    __nv_bfloat162 h3 = __floats2bfloat162_rn(b.z, b.w);
    uint4 v;
    v.x = *reinterpret_cast<uint32_t*>(&h0);
    v.y = *reinterpret_cast<uint32_t*>(&h1);
    v.z = *reinterpret_cast<uint32_t*>(&h2);
    v.w = *reinterpret_cast<uint32_t*>(&h3);
    size_t dst = ((size_t)((mt * NKC + kc) * 128u + r) * 8u + (c4 ^ (r & 7u))) * 16u;
    *reinterpret_cast<uint4*>(g_A + dst) = v;
}

// w [K,C] fp32 -> g_Bt bf16 transposed: Bt[n,k] = w[k,n], same tiled+swizzled layout.
// Also emits per-8-element partial sum-of-squares (fused ||w_c||^2 reduction stage 1).
__global__ void pack_w_kernel(const float* __restrict__ w) {
    unsigned id = blockIdx.x * blockDim.x + threadIdx.x;  // 262144 16B-chunks
    unsigned c4 = id & 7u, r = (id >> 3) & 127u, kc = (id >> 10) & 7u, nt = id >> 13;
    unsigned n = nt * 128u + r;
    unsigned kb = kc * 64u + c4 * 8u;
    float f[8];
#pragma unroll
    for (int j = 0; j < 8; j++) f[j] = w[(size_t)(kb + j) * C_COLS + n];
    float ss = 0.f;
#pragma unroll
    for (int j = 0; j < 8; j++) ss = fmaf(f[j], f[j], ss);
    g_wpart[(size_t)n * 64u + kc * 8u + c4] = ss;
    __nv_bfloat162 h0 = __floats2bfloat162_rn(f[0], f[1]);
    __nv_bfloat162 h1 = __floats2bfloat162_rn(f[2], f[3]);
    __nv_bfloat162 h2 = __floats2bfloat162_rn(f[4], f[5]);
    __nv_bfloat162 h3 = __floats2bfloat162_rn(f[6], f[7]);
    uint4 v;
    v.x = *reinterpret_cast<uint32_t*>(&h0);
    v.y = *reinterpret_cast<uint32_t*>(&h1);
    v.z = *reinterpret_cast<uint32_t*>(&h2);
    v.w = *reinterpret_cast<uint32_t*>(&h3);
    size_t dst = ((size_t)((nt * NKC + kc) * 128u + r) * 8u + (c4 ^ (r & 7u))) * 16u;
    *reinterpret_cast<uint4*>(g_Bt + dst) = v;
}

// Stage 2: warp-per-row/column, coalesced partial reads + shuffle reduce.
// Blocks [0,1024): x rows -> g_xn. Blocks [1024,1536): w cols -> g_p, g_q.
__global__ void finalize_kernel(const float* __restrict__ s) {
    int wid = threadIdx.x >> 5, lid = threadIdx.x & 31;
    int blk = blockIdx.x;
    if (blk < 1024) {
        int m = blk * 8 + wid;
        float v = g_xpart[(size_t)m * 64 + lid] + g_xpart[(size_t)m * 64 + 32 + lid];
#pragma unroll
        for (int off = 16; off; off >>= 1) v += __shfl_xor_sync(0xFFFFFFFFu, v, off);
        if (lid == 0) g_xn[m] = v;
    } else {
        int c = (blk - 1024) * 8 + wid;
        float v = g_wpart[(size_t)c * 64 + lid] + g_wpart[(size_t)c * 64 + 32 + lid];
#pragma unroll
        for (int off = 16; off; off >>= 1) v += __shfl_xor_sync(0xFFFFFFFFu, v, off);
        if (lid == 0) {
            float sv = s[c];
            float p = 1.0f / (sv * sv);
            g_p[c] = p;
            g_q[c] = 0.5f * v * p;
        }
    }
}

// ============================ GEMM + epilogue ============================
// smem: A0 A1 B0 B1, 16KB each. 256 threads: each copies 4 x 16B per tile.
__device__ __forceinline__ void load_chunk(uint32_t sb, int mt, int nt, int c, int buf, int tid) {
    const unsigned char* gA = g_A  + (size_t)(mt * NKC + c) * CHUNK_BYTES;
    const unsigned char* gB = g_Bt + (size_t)(nt * NKC + c) * CHUNK_BYTES;
    uint32_t sA = sb + buf * CHUNK_BYTES;
    uint32_t sB = sb + 2 * CHUNK_BYTES + buf * CHUNK_BYTES;
#pragma unroll
    for (int i = 0; i < 4; i++) {
        int o = (tid + i * 256) * 16;
        cp_async16(sA + o, gA + o);
    }
#pragma unroll
    for (int i = 0; i < 4; i++) {
        int o = (tid + i * 256) * 16;
        cp_async16(sB + o, gB + o);
    }
    CP_ASYNC_COMMIT();
}

__global__ __launch_bounds__(256) void rbf_gemm_kernel(float* __restrict__ out) {
    extern __shared__ __align__(1024) unsigned char smem[]; // 64KB
    __shared__ float s_p[TN], s_q[TN], s_xn[TM];

    int tid = threadIdx.x, lane = tid & 31, wid = tid >> 5;
    int wm = wid >> 1;          // 0..3 -> 32-row block
    int wn = wid & 1;           // 0..1 -> 64-col block
    int nt = blockIdx.x, mt = blockIdx.y;
    uint32_t sb = smem_u32(smem);

    if (tid < TN) {
        s_p[tid]  = g_p[nt * TN + tid];
        s_q[tid]  = g_q[nt * TN + tid];
        s_xn[tid] = g_xn[mt * TM + tid];
    }
    load_chunk(sb, mt, nt, 0, 0, tid);   // preload chunk 0

    float d[2][8][4];
#pragma unroll
    for (int mi = 0; mi < 2; mi++)
#pragma unroll
        for (int ni = 0; ni < 8; ni++)
#pragma unroll
            for (int j = 0; j < 4; j++) d[mi][ni][j] = 0.f;

    unsigned row16 = (unsigned)(lane & 15);  // ldmatrix row within 16-row block
    unsigned t     = (unsigned)(lane >> 4);  // 16B chunk parity (k8 half)

#pragma unroll 1
    for (int c = 0; c < NKC; c++) {
        if (c + 1 < NKC) load_chunk(sb, mt, nt, c + 1, (c + 1) & 1, tid);
        if (c + 1 < NKC) cp_async_wait_group<1>(); else cp_async_wait_group<0>();
        __syncthreads();

        uint32_t sA = sb + (c & 1) * CHUNK_BYTES;
        uint32_t sB = sb + 2 * CHUNK_BYTES + (c & 1) * CHUNK_BYTES;
#pragma unroll
        for (unsigned s = 0; s < 4; s++) {      // 4 x k16 steps cover KC=64
            uint32_t a[2][4];
#pragma unroll
            for (unsigned mi = 0; mi < 2; mi++) {
                unsigned row = (unsigned)wm * 32u + mi * 16u + row16;
                unsigned chunk = (t ^ (row & 7u)) ^ (2u * s);
                ldmatrix_x4(a[mi], sA + row * 128u + (chunk << 4));
            }
            uint32_t bb[4][4];
#pragma unroll
            for (unsigned nj = 0; nj < 4; nj++) {
                unsigned nrow = (unsigned)wn * 64u + nj * 16u + row16;
                unsigned chunk = (t ^ (nrow & 7u)) ^ (2u * s);
                ldmatrix_x4(bb[nj], sB + nrow * 128u + (chunk << 4));
            }
#pragma unroll
            for (int mi = 0; mi < 2; mi++)
#pragma unroll
                for (int ni = 0; ni < 8; ni++) {
                    int nj = ni >> 1, h = ni & 1;
                    mma16816(d[mi][ni], a[mi], bb[nj][h], bb[nj][h + 2]);
                }
        }
        __syncthreads();   // all warps done with buf (c&1) before it is refilled
    }

    // epilogue: arg = (xw - 0.5*||x||^2)*p_c - q_c ; out = exp(arg), with exact
    // flush-to-zero fast path (fp32 exp underflows to 0 for arg < -103.98).
    // Streaming stores (.cs): output is write-once; don't evict L2-resident A/B.
#pragma unroll
    for (int mi = 0; mi < 2; mi++) {
        int rloc = wm * 32 + mi * 16 + (lane >> 2);
        float h0 = 0.5f * s_xn[rloc];
        float h1 = 0.5f * s_xn[rloc + 8];
        float* row0 = out + (size_t)(mt * TM + rloc) * C_COLS + nt * TN + wn * 64;
        float* row1 = row0 + 8 * C_COLS;
#pragma unroll
        for (int ni = 0; ni < 8; ni++) {
            int cl = wn * 64 + ni * 8 + (lane & 3) * 2;
            float p0 = s_p[cl], p1 = s_p[cl + 1];
            float q0 = s_q[cl], q1 = s_q[cl + 1];
            float a0 = fmaf(d[mi][ni][0] - h0, p0, -q0);
            float a1 = fmaf(d[mi][ni][1] - h0, p1, -q1);
            float a2 = fmaf(d[mi][ni][2] - h1, p0, -q0);
            float a3 = fmaf(d[mi][ni][3] - h1, p1, -q1);
            float2 v01, v23;
            v01.x = (a0 > -110.0f) ? __expf(a0) : 0.0f;
            v01.y = (a1 > -110.0f) ? __expf(a1) : 0.0f;
            v23.x = (a2 > -110.0f) ? __expf(a2) : 0.0f;
            v23.y = (a3 > -110.0f) ? __expf(a3) : 0.0f;
            int off = ni * 8 + (lane & 3) * 2;
            stcs_f2(row0 + off, v01);
            stcs_f2(row1 + off, v23);
        }
    }
}

// ============================ launch ============================
extern "C" void kernel_launch(void* const* d_in, const int* in_sizes, int n_in,
                              void* d_out, int out_size) {
    const float* x = (const float*)d_in[0];   // [8192, 512]
    const float* w = (const float*)d_in[1];   // [512, 4096]
    const float* s = (const float*)d_in[2];   // [1, 4096]
    float* out = (float*)d_out;               // [8192, 4096]

    (void)cudaFuncSetAttribute(rbf_gemm_kernel,
                               cudaFuncAttributeMaxDynamicSharedMemorySize, 4 * CHUNK_BYTES);

    pack_x_kernel<<<2048, 256>>>(x);
    pack_w_kernel<<<1024, 256>>>(w);
    finalize_kernel<<<1536, 256>>>(s);

    dim3 grid(NT, MT);   // (32, 64)
    rbf_gemm_kernel<<<grid, 256, 4 * CHUNK_BYTES>>>(out);
}